// round 4
// baseline (speedup 1.0000x reference)
#include <cuda_runtime.h>
#include <math.h>

#define T 20
#define NC 80
#define BS 32

__constant__ float c_anch[3][3][2] = {
    {{116.f, 90.f}, {156.f, 198.f}, {373.f, 326.f}},
    {{ 30.f, 61.f}, { 62.f,  45.f}, { 59.f, 119.f}},
    {{ 10.f, 13.f}, { 16.f,  30.f}, { 33.f,  23.f}}
};

__device__ __forceinline__ float tanh_ap(float x) {
    float r; asm("tanh.approx.f32 %0, %1;" : "=f"(r) : "f"(x)); return r;
}
// stable softplus, fast intrinsics
__device__ __forceinline__ float sp(float z) {
    return fmaxf(z, 0.f) + __logf(1.f + __expf(-fabsf(z)));
}

struct SMem {
    float4 box[T];     // target box, grid units (degenerate if invalid)
    float4 tgt[T];     // tx,ty,tw,th
    float  aeps[T];    // area + 1e-16
    int    flat[T];    // -1 if invalid
    int    lab[T];
    int    pos[512];   // winning target per block-local cell
    float  wred[4];
};

template<int LVL, int W, int HW, bool VEC>
__device__ __forceinline__ void level_body(
    SMem& sm, int nblk, int b,
    const float* __restrict__ x,
    const float* __restrict__ gtb,
    const int*   __restrict__ gtl,
    float* __restrict__ out)
{
    constexpr int   N      = 3 * HW;
    constexpr float stride = (LVL == 0) ? 32.f : (LVL == 1) ? 16.f : 8.f;
    const float inv_s = 1.f / stride;
    const int tid  = threadIdx.x;
    const int lane = tid & 31;
    const int wrp  = tid >> 5;

    float sax[3], say[3];
#pragma unroll
    for (int a = 0; a < 3; a++) {
        sax[a] = c_anch[LVL][a][0] * inv_s;
        say[a] = c_anch[LVL][a][1] * inv_s;
    }

    const int base = nblk * 512;

    // ---- phase A: init pos table + per-target precompute ----
#pragma unroll
    for (int c = 0; c < 4; c++) sm.pos[4 * tid + c] = -1;

    if (tid < T) {
        const float* g = gtb + ((size_t)b * T + tid) * 4;
        float a1 = g[0], b1 = g[1], a2 = g[2], b2 = g[3];
        bool valid = (a1 != -1.f) || (b1 != -1.f) || (a2 != -1.f) || (b2 != -1.f);

        float tbx1 = a1 * inv_s, tby1 = b1 * inv_s;
        float tbx2 = a2 * inv_s, tby2 = b2 * inv_s;
        if (!valid) { tbx1 = tby1 = tbx2 = tby2 = 0.f; }
        sm.box[tid]  = make_float4(tbx1, tby1, tbx2, tby2);
        sm.aeps[tid] = (tbx2 - tbx1) * (tby2 - tby1) + 1e-16f;

        float gw  = (a2 - a1) * inv_s;
        float gh  = (b2 - b1) * inv_s;
        float gxc = (a1 + a2) * (0.5f * inv_s);
        float gyc = (b1 + b2) * (0.5f * inv_s);
        int gi = min(max((int)gxc, 0), W - 1);
        int gj = min(max((int)gyc, 0), W - 1);

        int best = 0; float bi = -1.f;
#pragma unroll
        for (int a = 0; a < 3; a++) {
            float inter = fminf(gw, sax[a]) * fminf(gh, say[a]);
            float u = gw * gh + sax[a] * say[a] - inter + 1e-16f;
            float io = inter / u;
            if (io > bi) { bi = io; best = a; }
        }
        sm.flat[tid] = valid ? (best * HW + gj * W + gi) : -1;
        float bsx = (best == 0) ? sax[0] : (best == 1) ? sax[1] : sax[2];
        float bsy = (best == 0) ? say[0] : (best == 1) ? say[1] : say[2];
        sm.tgt[tid] = make_float4(gxc - (float)gi, gyc - (float)gj,
                                  logf(gw / bsx + 1e-16f),
                                  logf(gh / bsy + 1e-16f));
        sm.lab[tid] = min(max(gtl[b * T + tid], 0), NC - 1);
    }
    __syncthreads();

    // ---- phase B: scatter winners (last-writer == max t) ----
    if (tid < T) {
        int f = sm.flat[tid];
        int loc = f - base;
        if (f >= 0 && loc >= 0 && loc < 512) atomicMax(&sm.pos[loc], tid);
    }
    __syncthreads();

    const size_t base_b = (size_t)b * 255 * HW;

    // ---- load 4 cells + decode ----
    float zx[4], zy[4], zw[4], zh[4], zc[4];
    float bx1[4], by1[4], bx2[4], by2[4], ap[4];
    bool  act[4];
    int   offc[4];   // channel-0 element offset within this batch's tensor
    int   ic[4], jc[4], ac[4];

    if (VEC) {
        int n0 = base + 4 * tid;
        bool a_ = (n0 < N);             // N%4==0: all-or-nothing per group
        int aa   = n0 / HW;             // compile-time magic div
        int rem  = n0 - aa * HW;
        int off0 = aa * 85 * HW + rem;
        int j0   = rem / W;
        int i0   = rem - j0 * W;
#pragma unroll
        for (int c = 0; c < 4; c++) {
            act[c]  = a_;
            offc[c] = off0 + c;
            int ii = i0 + c, jj = j0;
            if (ii >= W) { ii -= W; jj++; }
            ic[c] = ii; jc[c] = jj; ac[c] = aa;
        }
        if (a_) {
            const float* xp = x + base_b + off0;
            float4 v;
            v = *(const float4*)(xp);            zx[0]=v.x; zx[1]=v.y; zx[2]=v.z; zx[3]=v.w;
            v = *(const float4*)(xp +     HW);   zy[0]=v.x; zy[1]=v.y; zy[2]=v.z; zy[3]=v.w;
            v = *(const float4*)(xp + 2 * HW);   zw[0]=v.x; zw[1]=v.y; zw[2]=v.z; zw[3]=v.w;
            v = *(const float4*)(xp + 3 * HW);   zh[0]=v.x; zh[1]=v.y; zh[2]=v.z; zh[3]=v.w;
            v = *(const float4*)(xp + 4 * HW);   zc[0]=v.x; zc[1]=v.y; zc[2]=v.z; zc[3]=v.w;
        } else {
#pragma unroll
            for (int c = 0; c < 4; c++) { zx[c]=zy[c]=zw[c]=zh[c]=zc[c]=0.f; }
        }
    } else {
#pragma unroll
        for (int c = 0; c < 4; c++) {
            int n = base + 4 * tid + c;
            act[c] = (n < N);
            int aa  = n / HW;           // compile-time magic div
            int rem = n - aa * HW;
            offc[c] = aa * 85 * HW + rem;
            int jj = rem / W;
            ic[c] = rem - jj * W; jc[c] = jj; ac[c] = aa;
            if (act[c]) {
                const float* xp = x + base_b + offc[c];
                zx[c] = xp[0];
                zy[c] = xp[HW];
                zw[c] = xp[2 * HW];
                zh[c] = xp[3 * HW];
                zc[c] = xp[4 * HW];
            } else {
                zx[c]=zy[c]=zw[c]=zh[c]=zc[c]=0.f;
            }
        }
    }

#pragma unroll
    for (int c = 0; c < 4; c++) {
        float sxo = 0.5f * tanh_ap(0.5f * zx[c]) + 0.5f;  // sigmoid
        float syo = 0.5f * tanh_ap(0.5f * zy[c]) + 0.5f;
        float cx = sxo + (float)ic[c];
        float cy = syo + (float)jc[c];
        int a = ac[c];
        float sxa = (a == 0) ? sax[0] : (a == 1) ? sax[1] : sax[2];
        float sya = (a == 0) ? say[0] : (a == 1) ? say[1] : say[2];
        float bw = __expf(zw[c]) * sxa;
        float bh = __expf(zh[c]) * sya;
        bx1[c] = cx - 0.5f * bw; by1[c] = cy - 0.5f * bh;
        bx2[c] = cx + 0.5f * bw; by2[c] = cy + 0.5f * bh;
        ap[c]  = bw * bh;
        if (!act[c]) { bx1[c] = 1e30f; by1[c] = 1e30f; bx2[c] = -1e30f; by2[c] = -1e30f; ap[c] = 1e30f; }
    }

    // per-lane union of its 4 pred boxes (conservative prune envelope)
    float ux1 = fminf(fminf(bx1[0], bx1[1]), fminf(bx1[2], bx1[3]));
    float uy1 = fminf(fminf(by1[0], by1[1]), fminf(by1[2], by1[3]));
    float ux2 = fmaxf(fmaxf(bx2[0], bx2[1]), fmaxf(bx2[2], bx2[3]));
    float uy2 = fmaxf(fmaxf(by2[0], by2[1]), fmaxf(by2[2], by2[3]));
    float mnp = fminf(fminf(ap[0], ap[1]), fminf(ap[2], ap[3]));

    // ---- pruned ignore loop ----
    int Lig[4] = {-1, -1, -1, -1};
#pragma unroll 2
    for (int t = 0; t < T; t++) {
        float4 bb = sm.box[t];
        float rhs = sm.aeps[t];
        float iwu = fminf(ux2, bb.z) - fmaxf(ux1, bb.x);
        float ihu = fminf(uy2, bb.w) - fmaxf(uy1, bb.y);
        float inu = fmaxf(iwu, 0.f) * fmaxf(ihu, 0.f);
        // conservative: union-inter >= per-cell inter, min-area <= per-cell area
        if (__any_sync(0xffffffffu, 3.f * inu > mnp + rhs)) {
#pragma unroll
            for (int c = 0; c < 4; c++) {
                float iw = fminf(bx2[c], bb.z) - fmaxf(bx1[c], bb.x);
                float ih = fminf(by2[c], bb.w) - fmaxf(by1[c], bb.y);
                float in_ = fmaxf(iw, 0.f) * fmaxf(ih, 0.f);
                if (3.f * in_ > ap[c] + rhs) Lig[c] = t;
            }
        }
    }

    // ---- loss assembly ----
    float loss = 0.f;
    float tprod = 1.f, bacc = 0.f;
    bool pos[4];
    unsigned m0[4], m1[4], m2[4];

#pragma unroll
    for (int c = 0; c < 4; c++) {
        int Lp = sm.pos[4 * tid + c];
        pos[c] = act[c] && (Lp >= 0) && (Lp >= Lig[c]);
        bool neg = act[c] && (Lig[c] < 0) && !pos[c];
        // batched negative-conf softplus: sp(z) = max(z,0) + log1p(e^-|z|)
        float tcv = __expf(-fabsf(zc[c]));
        tprod *= neg ? (1.f + tcv) : 1.f;
        bacc  += neg ? fmaxf(zc[c], 0.f) : 0.f;
        m0[c] = m1[c] = m2[c] = 0;
        if (pos[c]) {
            float4 tg = sm.tgt[Lp];
            float bxl = tg.x * sp(-zx[c]) + (1.f - tg.x) * sp(zx[c]);
            float byl = tg.y * sp(-zy[c]) + (1.f - tg.y) * sp(zy[c]);
            float dw = zw[c] - tg.z, dh = zh[c] - tg.w;
            loss += 2.5f * (bxl + byl + dw * dw + dh * dh) + sp(-zc[c]);
            int n_c = base + 4 * tid + c;
#pragma unroll
            for (int t = 0; t < T; t++)
                if (sm.flat[t] == n_c) {
                    int l = sm.lab[t];
                    if (l < 32)      m0[c] |= 1u << l;
                    else if (l < 64) m1[c] |= 1u << (l - 32);
                    else             m2[c] |= 1u << (l - 64);
                }
        }
    }
    loss += bacc + __logf(tprod);

    // ---- warp-cooperative class loss (rare positives) ----
    // BCE(sig(z),1) = sp(z) - z ; BCE(sig(z),0) = sp(z)
#pragma unroll
    for (int c = 0; c < 4; c++) {
        unsigned bal = __ballot_sync(0xffffffffu, pos[c]);
        while (bal) {
            int src = __ffs(bal) - 1;
            bal &= bal - 1;
            int off      = __shfl_sync(0xffffffffu, offc[c], src);
            unsigned M0  = __shfl_sync(0xffffffffu, m0[c], src);
            unsigned M1  = __shfl_sync(0xffffffffu, m1[c], src);
            unsigned M2  = __shfl_sync(0xffffffffu, m2[c], src);
            const float* cps = x + base_b + off + (size_t)5 * HW;
            float z = __ldg(cps + (size_t)lane * HW);
            float acc = sp(z) - (((M0 >> lane) & 1u) ? z : 0.f);
            z = __ldg(cps + (size_t)(lane + 32) * HW);
            acc += sp(z) - (((M1 >> lane) & 1u) ? z : 0.f);
            if (lane < 16) {
                z = __ldg(cps + (size_t)(lane + 64) * HW);
                acc += sp(z) - (((M2 >> lane) & 1u) ? z : 0.f);
            }
            loss += acc;
        }
    }

    // ---- reduction ----
#pragma unroll
    for (int o = 16; o > 0; o >>= 1)
        loss += __shfl_down_sync(0xffffffffu, loss, o);
    if (lane == 0) sm.wred[wrp] = loss;
    __syncthreads();
    if (tid == 0) {
        atomicAdd(out, (sm.wred[0] + sm.wred[1] + sm.wred[2] + sm.wred[3]) * (1.f / (float)BS));
    }
}

// grid: (21, 32). bx==0 -> lvl0 (scalar); [1,5) -> lvl1; [5,21) -> lvl2.
// 128 threads x 4 cells = 512 cells/block.
__global__ __launch_bounds__(128, 5)
void yolo_loss_kernel(const float* __restrict__ x0,
                      const float* __restrict__ x1,
                      const float* __restrict__ x2,
                      const float* __restrict__ gtb,
                      const int*   __restrict__ gtl,
                      float* __restrict__ out)
{
    __shared__ SMem sm;
    const int bx = blockIdx.x;
    const int b  = blockIdx.y;
    if (bx == 0)      level_body<0, 13, 169,  false>(sm, 0,      b, x0, gtb, gtl, out);
    else if (bx < 5)  level_body<1, 26, 676,  true >(sm, bx - 1, b, x1, gtb, gtl, out);
    else              level_body<2, 52, 2704, true >(sm, bx - 5, b, x2, gtb, gtl, out);
}

extern "C" void kernel_launch(void* const* d_in, const int* in_sizes, int n_in,
                              void* d_out, int out_size)
{
    const float* x0  = (const float*)d_in[0];
    const float* x1  = (const float*)d_in[1];
    const float* x2  = (const float*)d_in[2];
    const float* gtb = (const float*)d_in[3];
    const int*   gtl = (const int*)  d_in[4];
    float* out = (float*)d_out;

    cudaMemsetAsync(out, 0, sizeof(float));
    dim3 grid(21, BS);
    yolo_loss_kernel<<<grid, 128>>>(x0, x1, x2, gtb, gtl, out);
}

// round 5
// speedup vs baseline: 1.2339x; 1.2339x over previous
#include <cuda_runtime.h>
#include <math.h>

#define T 20
#define NC 80
#define BS 32

__constant__ float c_anch[3][3][2] = {
    {{116.f, 90.f}, {156.f, 198.f}, {373.f, 326.f}},
    {{ 30.f, 61.f}, { 62.f,  45.f}, { 59.f, 119.f}},
    {{ 10.f, 13.f}, { 16.f,  30.f}, { 33.f,  23.f}}
};

__device__ __forceinline__ float tanh_ap(float x) {
    float r; asm("tanh.approx.f32 %0, %1;" : "=f"(r) : "f"(x)); return r;
}
// stable softplus, fast intrinsics
__device__ __forceinline__ float sp(float z) {
    return fmaxf(z, 0.f) + __logf(1.f + __expf(-fabsf(z)));
}

struct SMem {
    float4 box[T];     // target box, grid units (degenerate if invalid)
    float4 tgt[T];     // tx,ty,tw,th
    float  aeps[T];    // area + 1e-16
    int    flat[T];    // -1 if invalid
    int    lab[T];
    int    pos[512];   // winning target per block-local cell
    float  wred[8];
};

template<int LVL, int W, int HW, bool VEC>
__device__ __forceinline__ void level_body(
    SMem& sm, int nblk, int b,
    const float* __restrict__ x,
    const float* __restrict__ gtb,
    const int*   __restrict__ gtl,
    float* __restrict__ out)
{
    constexpr int   N      = 3 * HW;
    constexpr float stride = (LVL == 0) ? 32.f : (LVL == 1) ? 16.f : 8.f;
    const float inv_s = 1.f / stride;
    const int tid  = threadIdx.x;
    const int lane = tid & 31;
    const int wrp  = tid >> 5;

    float sax[3], say[3];
#pragma unroll
    for (int a = 0; a < 3; a++) {
        sax[a] = c_anch[LVL][a][0] * inv_s;
        say[a] = c_anch[LVL][a][1] * inv_s;
    }

    const int base = nblk * 512;

    // ---- phase A: init pos table + per-target precompute ----
    sm.pos[2 * tid]     = -1;
    sm.pos[2 * tid + 1] = -1;

    if (tid < T) {
        const float* g = gtb + ((size_t)b * T + tid) * 4;
        float a1 = g[0], b1 = g[1], a2 = g[2], b2 = g[3];
        bool valid = (a1 != -1.f) || (b1 != -1.f) || (a2 != -1.f) || (b2 != -1.f);

        float tbx1 = a1 * inv_s, tby1 = b1 * inv_s;
        float tbx2 = a2 * inv_s, tby2 = b2 * inv_s;
        if (!valid) { tbx1 = tby1 = tbx2 = tby2 = 0.f; }
        sm.box[tid]  = make_float4(tbx1, tby1, tbx2, tby2);
        sm.aeps[tid] = (tbx2 - tbx1) * (tby2 - tby1) + 1e-16f;

        float gw  = (a2 - a1) * inv_s;
        float gh  = (b2 - b1) * inv_s;
        float gxc = (a1 + a2) * (0.5f * inv_s);
        float gyc = (b1 + b2) * (0.5f * inv_s);
        int gi = min(max((int)gxc, 0), W - 1);
        int gj = min(max((int)gyc, 0), W - 1);

        int best = 0; float bi = -1.f;
#pragma unroll
        for (int a = 0; a < 3; a++) {
            float inter = fminf(gw, sax[a]) * fminf(gh, say[a]);
            float u = gw * gh + sax[a] * say[a] - inter + 1e-16f;
            float io = inter / u;
            if (io > bi) { bi = io; best = a; }
        }
        sm.flat[tid] = valid ? (best * HW + gj * W + gi) : -1;
        float bsx = (best == 0) ? sax[0] : (best == 1) ? sax[1] : sax[2];
        float bsy = (best == 0) ? say[0] : (best == 1) ? say[1] : say[2];
        sm.tgt[tid] = make_float4(gxc - (float)gi, gyc - (float)gj,
                                  logf(gw / bsx + 1e-16f),
                                  logf(gh / bsy + 1e-16f));
        sm.lab[tid] = min(max(gtl[b * T + tid], 0), NC - 1);
    }
    __syncthreads();

    // ---- phase B: scatter winners (last-writer == max t) ----
    if (tid < T) {
        int f = sm.flat[tid];
        int loc = f - base;
        if (f >= 0 && loc >= 0 && loc < 512) atomicMax(&sm.pos[loc], tid);
    }
    __syncthreads();

    const size_t base_b = (size_t)b * 255 * HW;

    // ---- load 2 adjacent cells + decode ----
    float zx[2], zy[2], zw[2], zh[2], zc[2];
    float bx1[2], by1[2], bx2[2], by2[2], ap[2];
    bool  act[2];
    int   offc[2], ic[2], jc[2], ac[2];

    const int n0 = base + 2 * tid;      // even
    {
        int aa  = n0 / HW;              // compile-time magic div
        int rem = n0 - aa * HW;
        int j0  = rem / W;
        int i0  = rem - j0 * W;
        int off0 = aa * 85 * HW + rem;
#pragma unroll
        for (int c = 0; c < 2; c++) {
            act[c]  = (n0 + c < N);
            offc[c] = off0 + c;
            int ii = i0 + c, jj = j0;
            if (ii >= W) { ii -= W; jj++; }
            ic[c] = ii; jc[c] = jj; ac[c] = aa;
        }
        if (VEC) {  // HW even -> n0 even -> 8B-aligned float2 loads
            if (act[0]) {
                const float* xp = x + base_b + off0;
                float2 v;
                v = *(const float2*)(xp);          zx[0]=v.x; zx[1]=v.y;
                v = *(const float2*)(xp +     HW); zy[0]=v.x; zy[1]=v.y;
                v = *(const float2*)(xp + 2 * HW); zw[0]=v.x; zw[1]=v.y;
                v = *(const float2*)(xp + 3 * HW); zh[0]=v.x; zh[1]=v.y;
                v = *(const float2*)(xp + 4 * HW); zc[0]=v.x; zc[1]=v.y;
            } else {
#pragma unroll
                for (int c = 0; c < 2; c++) { zx[c]=zy[c]=zw[c]=zh[c]=zc[c]=0.f; }
            }
        } else {
#pragma unroll
            for (int c = 0; c < 2; c++) {
                if (act[c]) {
                    const float* xp = x + base_b + offc[c];
                    zx[c] = xp[0];
                    zy[c] = xp[HW];
                    zw[c] = xp[2 * HW];
                    zh[c] = xp[3 * HW];
                    zc[c] = xp[4 * HW];
                } else {
                    zx[c]=zy[c]=zw[c]=zh[c]=zc[c]=0.f;
                }
            }
        }
    }

#pragma unroll
    for (int c = 0; c < 2; c++) {
        float sxo = 0.5f * tanh_ap(0.5f * zx[c]) + 0.5f;  // sigmoid (threshold-only)
        float syo = 0.5f * tanh_ap(0.5f * zy[c]) + 0.5f;
        float cx = sxo + (float)ic[c];
        float cy = syo + (float)jc[c];
        int a = ac[c];
        float sxa = (a == 0) ? sax[0] : (a == 1) ? sax[1] : sax[2];
        float sya = (a == 0) ? say[0] : (a == 1) ? say[1] : say[2];
        float bw = __expf(zw[c]) * sxa;
        float bh = __expf(zh[c]) * sya;
        bx1[c] = cx - 0.5f * bw; by1[c] = cy - 0.5f * bh;
        bx2[c] = cx + 0.5f * bw; by2[c] = cy + 0.5f * bh;
        ap[c]  = bw * bh;
        if (!act[c]) { bx1[c] = 1e30f; by1[c] = 1e30f; bx2[c] = -1e30f; by2[c] = -1e30f; ap[c] = 1e30f; }
    }

    // ---- ignore loop, 2 independent chains ----
    int Lig0 = -1, Lig1 = -1;
#pragma unroll
    for (int t = 0; t < T; t++) {
        float4 bb = sm.box[t];
        float rhs = sm.aeps[t];
        float iw0 = fminf(bx2[0], bb.z) - fmaxf(bx1[0], bb.x);
        float ih0 = fminf(by2[0], bb.w) - fmaxf(by1[0], bb.y);
        float in0 = fmaxf(iw0, 0.f) * fmaxf(ih0, 0.f);
        if (3.f * in0 > ap[0] + rhs) Lig0 = t;
        float iw1 = fminf(bx2[1], bb.z) - fmaxf(bx1[1], bb.x);
        float ih1 = fminf(by2[1], bb.w) - fmaxf(by1[1], bb.y);
        float in1 = fmaxf(iw1, 0.f) * fmaxf(ih1, 0.f);
        if (3.f * in1 > ap[1] + rhs) Lig1 = t;
    }

    // ---- loss assembly ----
    float loss = 0.f;
    float tprod = 1.f, bacc = 0.f;
    bool pos[2];
    unsigned m0[2], m1[2], m2[2];
    int Lig[2] = {Lig0, Lig1};

#pragma unroll
    for (int c = 0; c < 2; c++) {
        int Lp = sm.pos[2 * tid + c];
        pos[c] = act[c] && (Lp >= 0) && (Lp >= Lig[c]);
        bool neg = act[c] && (Lig[c] < 0) && !pos[c];
        // batched negative-conf softplus: sp(z) = max(z,0) + log1p(e^-|z|)
        float e = __expf(-fabsf(zc[c]));
        tprod *= neg ? (1.f + e) : 1.f;
        bacc  += neg ? fmaxf(zc[c], 0.f) : 0.f;
        m0[c] = m1[c] = m2[c] = 0;
        if (pos[c]) {
            float4 tg = sm.tgt[Lp];
            float bxl = tg.x * sp(-zx[c]) + (1.f - tg.x) * sp(zx[c]);
            float byl = tg.y * sp(-zy[c]) + (1.f - tg.y) * sp(zy[c]);
            float dw = zw[c] - tg.z, dh = zh[c] - tg.w;
            loss += 2.5f * (bxl + byl + dw * dw + dh * dh) + sp(-zc[c]);
            int n_c = n0 + c;
#pragma unroll
            for (int t = 0; t < T; t++)
                if (sm.flat[t] == n_c) {
                    int l = sm.lab[t];
                    if (l < 32)      m0[c] |= 1u << l;
                    else if (l < 64) m1[c] |= 1u << (l - 32);
                    else             m2[c] |= 1u << (l - 64);
                }
        }
    }
    loss += bacc + __logf(tprod);

    // ---- warp-cooperative class loss (rare positives) ----
    // BCE(sig(z),1) = sp(z) - z ; BCE(sig(z),0) = sp(z)
#pragma unroll
    for (int c = 0; c < 2; c++) {
        unsigned bal = __ballot_sync(0xffffffffu, pos[c]);
        while (bal) {
            int src = __ffs(bal) - 1;
            bal &= bal - 1;
            int off      = __shfl_sync(0xffffffffu, offc[c], src);
            unsigned M0  = __shfl_sync(0xffffffffu, m0[c], src);
            unsigned M1  = __shfl_sync(0xffffffffu, m1[c], src);
            unsigned M2  = __shfl_sync(0xffffffffu, m2[c], src);
            const float* cps = x + base_b + off + (size_t)5 * HW;
            float z = __ldg(cps + (size_t)lane * HW);
            float acc = sp(z) - (((M0 >> lane) & 1u) ? z : 0.f);
            z = __ldg(cps + (size_t)(lane + 32) * HW);
            acc += sp(z) - (((M1 >> lane) & 1u) ? z : 0.f);
            if (lane < 16) {
                z = __ldg(cps + (size_t)(lane + 64) * HW);
                acc += sp(z) - (((M2 >> lane) & 1u) ? z : 0.f);
            }
            loss += acc;
        }
    }

    // ---- reduction ----
#pragma unroll
    for (int o = 16; o > 0; o >>= 1)
        loss += __shfl_down_sync(0xffffffffu, loss, o);
    if (lane == 0) sm.wred[wrp] = loss;
    __syncthreads();
    if (wrp == 0) {
        float v = (lane < 8) ? sm.wred[lane] : 0.f;
#pragma unroll
        for (int o = 4; o > 0; o >>= 1)
            v += __shfl_down_sync(0xffffffffu, v, o);
        if (lane == 0) atomicAdd(out, v * (1.f / (float)BS));
    }
}

// grid: (21, 32). bx==0 -> lvl0 (scalar); [1,5) -> lvl1; [5,21) -> lvl2.
// 256 threads x 2 cells = 512 cells/block.
__global__ __launch_bounds__(256)
void yolo_loss_kernel(const float* __restrict__ x0,
                      const float* __restrict__ x1,
                      const float* __restrict__ x2,
                      const float* __restrict__ gtb,
                      const int*   __restrict__ gtl,
                      float* __restrict__ out)
{
    __shared__ SMem sm;
    const int bx = blockIdx.x;
    const int b  = blockIdx.y;
    if (bx == 0)      level_body<0, 13, 169,  false>(sm, 0,      b, x0, gtb, gtl, out);
    else if (bx < 5)  level_body<1, 26, 676,  true >(sm, bx - 1, b, x1, gtb, gtl, out);
    else              level_body<2, 52, 2704, true >(sm, bx - 5, b, x2, gtb, gtl, out);
}

extern "C" void kernel_launch(void* const* d_in, const int* in_sizes, int n_in,
                              void* d_out, int out_size)
{
    const float* x0  = (const float*)d_in[0];
    const float* x1  = (const float*)d_in[1];
    const float* x2  = (const float*)d_in[2];
    const float* gtb = (const float*)d_in[3];
    const int*   gtl = (const int*)  d_in[4];
    float* out = (float*)d_out;

    cudaMemsetAsync(out, 0, sizeof(float));
    dim3 grid(21, BS);
    yolo_loss_kernel<<<grid, 256>>>(x0, x1, x2, gtb, gtl, out);
}

// round 6
// speedup vs baseline: 1.3518x; 1.0956x over previous
#include <cuda_runtime.h>
#include <math.h>

#define T 20
#define NC 80
#define BS 32

__constant__ float c_anch[3][3][2] = {
    {{116.f, 90.f}, {156.f, 198.f}, {373.f, 326.f}},
    {{ 30.f, 61.f}, { 62.f,  45.f}, { 59.f, 119.f}},
    {{ 10.f, 13.f}, { 16.f,  30.f}, { 33.f,  23.f}}
};

__device__ __forceinline__ float tanh_ap(float x) {
    float r; asm("tanh.approx.f32 %0, %1;" : "=f"(r) : "f"(x)); return r;
}
// stable softplus, fast intrinsics
__device__ __forceinline__ float sp(float z) {
    return fmaxf(z, 0.f) + __logf(1.f + __expf(-fabsf(z)));
}

struct SMem {
    float4 box[T];     // target box, grid units (degenerate if invalid)
    float4 tgt[T];     // tx,ty,tw,th
    float  aeps[T];    // area + 1e-16
    int    flat[T];    // -1 if invalid
    int    lab[T];
    int    pos[512];   // winning target per block-local cell
    float  wred[8];
};

template<int LVL, int W, int HW>
__device__ __forceinline__ void level_body(
    SMem& sm, int nblk, int b,
    const float* __restrict__ x,
    const float* __restrict__ gtb,
    const int*   __restrict__ gtl,
    float* __restrict__ out)
{
    constexpr int   N      = 3 * HW;
    constexpr float stride = (LVL == 0) ? 32.f : (LVL == 1) ? 16.f : 8.f;
    constexpr float inv_s  = 1.f / stride;
    const int tid  = threadIdx.x;
    const int lane = tid & 31;
    const int wrp  = tid >> 5;

    float sax[3], say[3];
#pragma unroll
    for (int a = 0; a < 3; a++) {
        sax[a] = c_anch[LVL][a][0] * inv_s;
        say[a] = c_anch[LVL][a][1] * inv_s;
    }

    const int base = nblk * 512;

    // ---- phase A: init pos table + per-target precompute ----
    sm.pos[tid]       = -1;
    sm.pos[tid + 256] = -1;
    if (tid < T) {
        const float* g = gtb + ((size_t)b * T + tid) * 4;
        float a1 = g[0], b1 = g[1], a2 = g[2], b2 = g[3];
        bool valid = (a1 != -1.f) || (b1 != -1.f) || (a2 != -1.f) || (b2 != -1.f);

        float tbx1 = a1 * inv_s, tby1 = b1 * inv_s;
        float tbx2 = a2 * inv_s, tby2 = b2 * inv_s;
        if (!valid) { tbx1 = tby1 = tbx2 = tby2 = 0.f; }
        sm.box[tid]  = make_float4(tbx1, tby1, tbx2, tby2);
        sm.aeps[tid] = (tbx2 - tbx1) * (tby2 - tby1) + 1e-16f;

        float gw  = (a2 - a1) * inv_s;
        float gh  = (b2 - b1) * inv_s;
        float gxc = (a1 + a2) * (0.5f * inv_s);
        float gyc = (b1 + b2) * (0.5f * inv_s);
        int gi = min(max((int)gxc, 0), W - 1);
        int gj = min(max((int)gyc, 0), W - 1);

        int best = 0; float bi = -1.f;
#pragma unroll
        for (int a = 0; a < 3; a++) {
            float inter = fminf(gw, sax[a]) * fminf(gh, say[a]);
            float u = gw * gh + sax[a] * say[a] - inter + 1e-16f;
            float io = inter / u;
            if (io > bi) { bi = io; best = a; }
        }
        sm.flat[tid] = valid ? (best * HW + gj * W + gi) : -1;
        float bsx = (best == 0) ? sax[0] : (best == 1) ? sax[1] : sax[2];
        float bsy = (best == 0) ? say[0] : (best == 1) ? say[1] : say[2];
        sm.tgt[tid] = make_float4(gxc - (float)gi, gyc - (float)gj,
                                  logf(gw / bsx + 1e-16f),
                                  logf(gh / bsy + 1e-16f));
        sm.lab[tid] = min(max(gtl[b * T + tid], 0), NC - 1);
    }
    __syncthreads();

    // ---- phase B: scatter winners (last-writer == max t) ----
    if (tid < T) {
        int f = sm.flat[tid];
        int loc = f - base;
        if (f >= 0 && loc >= 0 && loc < 512) atomicMax(&sm.pos[loc], tid);
    }
    __syncthreads();

    // hoist LDS reads early (bury latency under the global loads)
    const int Lp0 = sm.pos[tid];
    const int Lp1 = sm.pos[tid + 256];

    const size_t base_b = (size_t)b * 255 * HW;

    const int n0 = base + tid;
    const int n1 = base + 256 + tid;
    const bool act0 = (n0 < N);
    const bool act1 = (n1 < N);

    // ---- load + decode both cells (strided => 2 independent chains) ----
    float zx0=0,zy0=0,zw0=0,zh0=0,zc0=0, zx1=0,zy1=0,zw1=0,zh1=0,zc1=0;
    float px1_0,py1_0,px2_0,py2_0,ap0;
    float px1_1,py1_1,px2_1,py2_1,ap1;
    int off0 = 0, off1 = 0;

    {
        int a0   = n0 / HW;             // compile-time magic div
        int rem0 = n0 - a0 * HW;
        int j0   = rem0 / W;
        int i0   = rem0 - j0 * W;
        off0     = a0 * (85 * HW) + rem0;
        int a1   = n1 / HW;
        int rem1 = n1 - a1 * HW;
        int j1   = rem1 / W;
        int i1   = rem1 - j1 * W;
        off1     = a1 * (85 * HW) + rem1;

        if (act0) {
            const float* xp = x + base_b + off0;
            zx0 = xp[0]; zy0 = xp[HW]; zw0 = xp[2*HW]; zh0 = xp[3*HW]; zc0 = xp[4*HW];
        }
        if (act1) {
            const float* xp = x + base_b + off1;
            zx1 = xp[0]; zy1 = xp[HW]; zw1 = xp[2*HW]; zh1 = xp[3*HW]; zc1 = xp[4*HW];
        }

        float sx = 0.5f * tanh_ap(0.5f * zx0) + 0.5f;
        float sy = 0.5f * tanh_ap(0.5f * zy0) + 0.5f;
        float cx = sx + (float)i0, cy = sy + (float)j0;
        float sxa = (a0 == 0) ? sax[0] : (a0 == 1) ? sax[1] : sax[2];
        float sya = (a0 == 0) ? say[0] : (a0 == 1) ? say[1] : say[2];
        float bw = __expf(zw0) * sxa, bh = __expf(zh0) * sya;
        px1_0 = cx - 0.5f*bw; py1_0 = cy - 0.5f*bh;
        px2_0 = cx + 0.5f*bw; py2_0 = cy + 0.5f*bh;
        ap0 = bw * bh;
        if (!act0) { px1_0 = py1_0 = 1e30f; px2_0 = py2_0 = -1e30f; ap0 = 1e30f; }

        sx = 0.5f * tanh_ap(0.5f * zx1) + 0.5f;
        sy = 0.5f * tanh_ap(0.5f * zy1) + 0.5f;
        cx = sx + (float)i1; cy = sy + (float)j1;
        sxa = (a1 == 0) ? sax[0] : (a1 == 1) ? sax[1] : sax[2];
        sya = (a1 == 0) ? say[0] : (a1 == 1) ? say[1] : say[2];
        bw = __expf(zw1) * sxa; bh = __expf(zh1) * sya;
        px1_1 = cx - 0.5f*bw; py1_1 = cy - 0.5f*bh;
        px2_1 = cx + 0.5f*bw; py2_1 = cy + 0.5f*bh;
        ap1 = bw * bh;
        if (!act1) { px1_1 = py1_1 = 1e30f; px2_1 = py2_1 = -1e30f; ap1 = 1e30f; }
    }

    // ---- ignore loop, 2 independent chains, fma-folded compare ----
    int Lig0 = -1, Lig1 = -1;
#pragma unroll
    for (int t = 0; t < T; t++) {
        float4 bb = sm.box[t];
        float rhs = sm.aeps[t];
        float iw0 = fminf(px2_0, bb.z) - fmaxf(px1_0, bb.x);
        float ih0 = fminf(py2_0, bb.w) - fmaxf(py1_0, bb.y);
        float in0 = fmaxf(iw0, 0.f) * fmaxf(ih0, 0.f);
        if (fmaf(3.f, in0, -ap0) > rhs) Lig0 = t;
        float iw1 = fminf(px2_1, bb.z) - fmaxf(px1_1, bb.x);
        float ih1 = fminf(py2_1, bb.w) - fmaxf(py1_1, bb.y);
        float in1 = fmaxf(iw1, 0.f) * fmaxf(ih1, 0.f);
        if (fmaf(3.f, in1, -ap1) > rhs) Lig1 = t;
    }

    const bool pos0 = act0 && (Lp0 >= 0) && (Lp0 >= Lig0);
    const bool pos1 = act1 && (Lp1 >= 0) && (Lp1 >= Lig1);

    // ---- loss assembly ----
    float loss = 0.f;
    // batched negative conf: sp(z) = max(z,0) + log1p(e^-|z|); product the log1p args
    bool neg0 = act0 && (Lig0 < 0) && !pos0;
    bool neg1 = act1 && (Lig1 < 0) && !pos1;
    float e0 = __expf(-fabsf(zc0));
    float e1 = __expf(-fabsf(zc1));
    float tprod = (neg0 ? (1.f + e0) : 1.f) * (neg1 ? (1.f + e1) : 1.f);
    float bacc  = (neg0 ? fmaxf(zc0, 0.f) : 0.f) + (neg1 ? fmaxf(zc1, 0.f) : 0.f);
    loss += bacc + __logf(tprod);

    unsigned m0a=0, m1a=0, m2a=0, m0b=0, m1b=0, m2b=0;
    if (pos0) {
        float4 tg = sm.tgt[Lp0];
        float bxl = tg.x * sp(-zx0) + (1.f - tg.x) * sp(zx0);
        float byl = tg.y * sp(-zy0) + (1.f - tg.y) * sp(zy0);
        float dw = zw0 - tg.z, dh = zh0 - tg.w;
        loss += 2.5f * (bxl + byl + dw*dw + dh*dh) + sp(-zc0);
#pragma unroll
        for (int t = 0; t < T; t++)
            if (sm.flat[t] == n0) {
                int l = sm.lab[t];
                if (l < 32) m0a |= 1u << l; else if (l < 64) m1a |= 1u << (l-32); else m2a |= 1u << (l-64);
            }
    }
    if (pos1) {
        float4 tg = sm.tgt[Lp1];
        float bxl = tg.x * sp(-zx1) + (1.f - tg.x) * sp(zx1);
        float byl = tg.y * sp(-zy1) + (1.f - tg.y) * sp(zy1);
        float dw = zw1 - tg.z, dh = zh1 - tg.w;
        loss += 2.5f * (bxl + byl + dw*dw + dh*dh) + sp(-zc1);
#pragma unroll
        for (int t = 0; t < T; t++)
            if (sm.flat[t] == n1) {
                int l = sm.lab[t];
                if (l < 32) m0b |= 1u << l; else if (l < 64) m1b |= 1u << (l-32); else m2b |= 1u << (l-64);
            }
    }

    // ---- warp-cooperative class loss (rare positives) ----
    // BCE(sig(z),1) = sp(z) - z ; BCE(sig(z),0) = sp(z)
#pragma unroll
    for (int c = 0; c < 2; c++) {
        bool p       = c ? pos1 : pos0;
        int  off     = c ? off1 : off0;
        unsigned M0t = c ? m0b : m0a, M1t = c ? m1b : m1a, M2t = c ? m2b : m2a;
        unsigned bal = __ballot_sync(0xffffffffu, p);
        while (bal) {
            int src = __ffs(bal) - 1;
            bal &= bal - 1;
            int offs    = __shfl_sync(0xffffffffu, off, src);
            unsigned M0 = __shfl_sync(0xffffffffu, M0t, src);
            unsigned M1 = __shfl_sync(0xffffffffu, M1t, src);
            unsigned M2 = __shfl_sync(0xffffffffu, M2t, src);
            const float* cps = x + base_b + offs + (size_t)5 * HW;
            float z = __ldg(cps + (size_t)lane * HW);
            float acc = sp(z) - (((M0 >> lane) & 1u) ? z : 0.f);
            z = __ldg(cps + (size_t)(lane + 32) * HW);
            acc += sp(z) - (((M1 >> lane) & 1u) ? z : 0.f);
            if (lane < 16) {
                z = __ldg(cps + (size_t)(lane + 64) * HW);
                acc += sp(z) - (((M2 >> lane) & 1u) ? z : 0.f);
            }
            loss += acc;
        }
    }

    // ---- reduction ----
#pragma unroll
    for (int o = 16; o > 0; o >>= 1)
        loss += __shfl_down_sync(0xffffffffu, loss, o);
    if (lane == 0) sm.wred[wrp] = loss;
    __syncthreads();
    if (wrp == 0) {
        float v = (lane < 8) ? sm.wred[lane] : 0.f;
#pragma unroll
        for (int o = 4; o > 0; o >>= 1)
            v += __shfl_down_sync(0xffffffffu, v, o);
        if (lane == 0) atomicAdd(out, v * (1.f / (float)BS));
    }
}

// grid: (21, 32). bx==0 -> lvl0; [1,5) -> lvl1; [5,21) -> lvl2.
// 256 threads x 2 strided cells = 512 cells/block.
__global__ __launch_bounds__(256)
void yolo_loss_kernel(const float* __restrict__ x0,
                      const float* __restrict__ x1,
                      const float* __restrict__ x2,
                      const float* __restrict__ gtb,
                      const int*   __restrict__ gtl,
                      float* __restrict__ out)
{
    __shared__ SMem sm;
    const int bx = blockIdx.x;
    const int b  = blockIdx.y;
    if (bx == 0)      level_body<0, 13, 169 >(sm, 0,      b, x0, gtb, gtl, out);
    else if (bx < 5)  level_body<1, 26, 676 >(sm, bx - 1, b, x1, gtb, gtl, out);
    else              level_body<2, 52, 2704>(sm, bx - 5, b, x2, gtb, gtl, out);
}

extern "C" void kernel_launch(void* const* d_in, const int* in_sizes, int n_in,
                              void* d_out, int out_size)
{
    const float* x0  = (const float*)d_in[0];
    const float* x1  = (const float*)d_in[1];
    const float* x2  = (const float*)d_in[2];
    const float* gtb = (const float*)d_in[3];
    const int*   gtl = (const int*)  d_in[4];
    float* out = (float*)d_out;

    cudaMemsetAsync(out, 0, sizeof(float));
    dim3 grid(21, BS);
    yolo_loss_kernel<<<grid, 256>>>(x0, x1, x2, gtb, gtl, out);
}